// round 14
// baseline (speedup 1.0000x reference)
#include <cuda_runtime.h>
#include <cstdint>

#define D        128
#define CD       3
#define NLAYERS  3
#define MAXN     65536
#define MAXE     1048576
#define SCAN_BS  256

// ---------------- scratch ----------------
__device__ float g_agg [(size_t)MAXN * D];
__device__ float g_xb  [(size_t)MAXN * D];
__device__ int   g_cnt [MAXN];            // zero-init; every call restores zeros
__device__ int   g_off [MAXN + 1];
__device__ int   g_srcs[MAXE];
__device__ int   g_bsum[(MAXN + SCAN_BS - 1) / SCAN_BS + 1];

// ---------------- CSR build ----------------
__global__ void hist_kernel(const int* __restrict__ dst, int* __restrict__ cnt, int E) {
    int i = blockIdx.x * blockDim.x + threadIdx.x;
    if (i < E) atomicAdd(&cnt[dst[i]], 1);
}

// stage 1: per-block exclusive scan of 256 counters; writes local prefix to off, block sum to bsum
__global__ __launch_bounds__(SCAN_BS) void scan1_kernel(
        const int* __restrict__ cnt, int* __restrict__ off, int* __restrict__ bsum, int n) {
    __shared__ int s[SCAN_BS];
    int t = threadIdx.x;
    int i = blockIdx.x * SCAN_BS + t;
    int v = (i < n) ? cnt[i] : 0;
    s[t] = v;
    __syncthreads();
    for (int d = 1; d < SCAN_BS; d <<= 1) {
        int u = (t >= d) ? s[t - d] : 0;
        __syncthreads();
        s[t] += u;
        __syncthreads();
    }
    if (i < n) off[i] = s[t] - v;          // local exclusive prefix
    if (t == SCAN_BS - 1) bsum[blockIdx.x] = s[t];
}

// stage 2: single block scans block sums (exclusive)
__global__ __launch_bounds__(1024) void scan2_kernel(int* __restrict__ bsum, int nb) {
    __shared__ int s[1024];
    int t = threadIdx.x;
    int v = (t < nb) ? bsum[t] : 0;
    s[t] = v;
    __syncthreads();
    for (int d = 1; d < 1024; d <<= 1) {
        int u = (t >= d) ? s[t - d] : 0;
        __syncthreads();
        s[t] += u;
        __syncthreads();
    }
    if (t < nb) bsum[t] = s[t] - v;        // exclusive base per block
}

// stage 3: add block base, reset cnt (restores zero-invariant for next call), write off[n]
__global__ __launch_bounds__(SCAN_BS) void scan3_kernel(
        int* __restrict__ cnt, int* __restrict__ off, const int* __restrict__ bsum,
        int n, int E) {
    int i = blockIdx.x * SCAN_BS + threadIdx.x;
    if (i < n) {
        off[i] += bsum[blockIdx.x];
        cnt[i] = 0;                        // reused as cursor by fill
    }
    if (i == 0) off[n] = E;
}

__global__ void fill_kernel(const int* __restrict__ src, const int* __restrict__ dst,
                            const int* __restrict__ off, int* __restrict__ cur,
                            int* __restrict__ srcs, int E) {
    int e = blockIdx.x * blockDim.x + threadIdx.x;
    if (e >= E) return;
    int d = dst[e];
    int p = atomicAdd(&cur[d], 1);
    srcs[off[d] + p] = src[e];
}

// after fill, cur[d] == deg[d]; reset happens in scan3 of the NEXT call? No —
// fill leaves cur=deg, breaking the next call's hist. So reset after use:
__global__ __launch_bounds__(SCAN_BS) void reset_cnt_kernel(int* __restrict__ cnt, int n) {
    int i = blockIdx.x * SCAN_BS + threadIdx.x;
    if (i < n) cnt[i] = 0;
}

// ---------------- 3x3 Householder QR (LAPACK dlarfg convention) ----------------
__device__ __forceinline__ void qr3(const float A0[9], float Q[9]) {
    float a[9];
#pragma unroll
    for (int i = 0; i < 9; i++) a[i] = A0[i];

    float tau1 = 0.f, v1 = 0.f, v2 = 0.f;
    {
        float c0 = a[0], c1 = a[3], c2 = a[6];
        float xn2 = c1 * c1 + c2 * c2;
        if (xn2 > 0.f) {
            float nrm  = sqrtf(c0 * c0 + xn2);
            float beta = -copysignf(nrm, c0);
            tau1 = (beta - c0) / beta;
            float inv = 1.f / (c0 - beta);
            v1 = c1 * inv;
            v2 = c2 * inv;
#pragma unroll
            for (int c = 1; c < 3; c++) {
                float w = a[c] + v1 * a[3 + c] + v2 * a[6 + c];
                w *= tau1;
                a[c]     -= w;
                a[3 + c] -= w * v1;
                a[6 + c] -= w * v2;
            }
        }
    }
    float tau2 = 0.f, u2 = 0.f;
    {
        float alpha = a[4], x2 = a[7];
        if (x2 != 0.f) {
            float nrm  = sqrtf(alpha * alpha + x2 * x2);
            float beta = -copysignf(nrm, alpha);
            tau2 = (beta - alpha) / beta;
            u2   = x2 / (alpha - beta);
        }
    }
    float h11 = 1.f - tau2;
    float h12 = -tau2 * u2;
    float h22 = 1.f - tau2 * u2 * u2;
#pragma unroll
    for (int j = 0; j < 3; j++) {
        float h0 = (j == 0) ? 1.f : 0.f;
        float h1 = (j == 0) ? 0.f : ((j == 1) ? h11 : h12);
        float h2 = (j == 0) ? 0.f : ((j == 1) ? h12 : h22);
        float w  = tau1 * (h0 + v1 * h1 + v2 * h2);
        Q[0 * 3 + j] = h0 - w;
        Q[1 * 3 + j] = h1 - v1 * w;
        Q[2 * 3 + j] = h2 - v2 * w;
    }
}

// ---------------- node update device body (warp-per-node) ----------------
__device__ __forceinline__ void node_update_body(
        const float* __restrict__ out, const float* sWp,
        const float* __restrict__ bc, const float* __restrict__ bR,
        const float* __restrict__ bt, const float* __restrict__ pos_in,
        float* __restrict__ pos, float* __restrict__ R, float* __restrict__ tv,
        int node, int lane, int first) {
    float4 xv = *(const float4*)&out[(size_t)node * D + lane * 4];
    float p[13];
#pragma unroll
    for (int j = 0; j < 13; j++) {
        float4 w = ((const float4*)&sWp[j * D])[lane];
        float s = xv.x * w.x + xv.y * w.y + xv.z * w.z + xv.w * w.w;
        s += __shfl_xor_sync(0xFFFFFFFF, s, 16);
        s += __shfl_xor_sync(0xFFFFFFFF, s, 8);
        s += __shfl_xor_sync(0xFFFFFFFF, s, 4);
        s += __shfl_xor_sync(0xFFFFFFFF, s, 2);
        s += __shfl_xor_sync(0xFFFFFFFF, s, 1);
        p[j] = s;
    }
    if (lane == 0) {
        float c = p[0] + bc[0];
        if (first) {
            pos[node * 3 + 0] = pos_in[node * 3 + 0] + c;
            pos[node * 3 + 1] = pos_in[node * 3 + 1] + c;
            pos[node * 3 + 2] = pos_in[node * 3 + 2] + c;
            tv[node * 3 + 0] = p[10] + bt[0];
            tv[node * 3 + 1] = p[11] + bt[1];
            tv[node * 3 + 2] = p[12] + bt[2];
        } else {
            pos[node * 3 + 0] += c;
            pos[node * 3 + 1] += c;
            pos[node * 3 + 2] += c;
            tv[node * 3 + 0] += p[10] + bt[0];
            tv[node * 3 + 1] += p[11] + bt[1];
            tv[node * 3 + 2] += p[12] + bt[2];
        }
        float Aq[9], Q[9];
#pragma unroll
        for (int i = 0; i < 9; i++) Aq[i] = p[1 + i] + bR[i];
        qr3(Aq, Q);
        if (first) {
#pragma unroll
            for (int i = 0; i < 9; i++) R[(size_t)node * 9 + i] = Q[i];
        } else {
            float Ro[9];
#pragma unroll
            for (int i = 0; i < 9; i++) Ro[i] = R[(size_t)node * 9 + i];
            float Rn[9];
#pragma unroll
            for (int i = 0; i < 3; i++)
#pragma unroll
                for (int j = 0; j < 3; j++)
                    Rn[i * 3 + j] = Q[i * 3 + 0] * Ro[0 * 3 + j]
                                  + Q[i * 3 + 1] * Ro[1 * 3 + j]
                                  + Q[i * 3 + 2] * Ro[2 * 3 + j];
#pragma unroll
            for (int i = 0; i < 9; i++) R[(size_t)node * 9 + i] = Rn[i];
        }
    }
}

__device__ __forceinline__ void load_proj_weights(
        float* sWp, const float* __restrict__ Wc, const float* __restrict__ WR,
        const float* __restrict__ Wt, int t, int nthreads) {
    for (int i = t; i < 13 * D; i += nthreads) {
        int j = i >> 7, k = i & 127;
        float v;
        if (j == 0)      v = Wc[k];
        else if (j < 10) v = WR[k * 9 + (j - 1)];
        else             v = Wt[k * 3 + (j - 10)];
        sWp[j * D + k] = v;
    }
}

// ---------------- aggregate device body (warp-per-node) ----------------
__device__ __forceinline__ void aggregate_body(
        const float4* __restrict__ x, const int* __restrict__ off,
        const int* __restrict__ srcs, float4* __restrict__ agg, int node, int lane) {
    int j0 = __ldg(&off[node]);
    int j1 = __ldg(&off[node + 1]);
    float4 acc = make_float4(0.f, 0.f, 0.f, 0.f);
    int j = j0;
    for (; j + 4 <= j1; j += 4) {
        int s0 = __ldg(&srcs[j + 0]);
        int s1 = __ldg(&srcs[j + 1]);
        int s2 = __ldg(&srcs[j + 2]);
        int s3 = __ldg(&srcs[j + 3]);
        float4 v0 = __ldg(&x[(size_t)s0 * 32 + lane]);
        float4 v1 = __ldg(&x[(size_t)s1 * 32 + lane]);
        float4 v2 = __ldg(&x[(size_t)s2 * 32 + lane]);
        float4 v3 = __ldg(&x[(size_t)s3 * 32 + lane]);
        acc.x += v0.x + v1.x + v2.x + v3.x;
        acc.y += v0.y + v1.y + v2.y + v3.y;
        acc.z += v0.z + v1.z + v2.z + v3.z;
        acc.w += v0.w + v1.w + v2.w + v3.w;
    }
    for (; j < j1; j++) {
        int s = __ldg(&srcs[j]);
        float4 v = __ldg(&x[(size_t)s * 32 + lane]);
        acc.x += v.x; acc.y += v.y; acc.z += v.z; acc.w += v.w;
    }
    agg[(size_t)node * 32 + lane] = acc;
}

// ---------------- plain aggregate ----------------
__global__ __launch_bounds__(256) void aggregate_kernel(
        const float4* __restrict__ x, const int* __restrict__ off,
        const int* __restrict__ srcs, float4* __restrict__ agg, int n) {
    int node = blockIdx.x * 8 + (threadIdx.x >> 5);
    if (node >= n) return;
    aggregate_body(x, off, srcs, agg, node, threadIdx.x & 31);
}

// ---------------- standalone node_update ----------------
__global__ __launch_bounds__(256) void node_update_kernel(
        const float* __restrict__ out,
        const float* __restrict__ Wc, const float* __restrict__ bc,
        const float* __restrict__ WR, const float* __restrict__ bR,
        const float* __restrict__ Wt, const float* __restrict__ bt,
        float* __restrict__ pos, float* __restrict__ R, float* __restrict__ tv, int n) {
    __shared__ float sWp[13 * D];
    int t = threadIdx.x;
    load_proj_weights(sWp, Wc, WR, Wt, t, 256);
    __syncthreads();
    int node = blockIdx.x * 8 + (t >> 5);
    if (node >= n) return;
    node_update_body(out, sWp, bc, bR, bt, nullptr, pos, R, tv, node, t & 31, 0);
}

// ---------------- fat kernel: aggregate(l+1) || node_update(l) ----------------
__global__ __launch_bounds__(256) void agg_update_kernel(
        const float4* __restrict__ x, const int* __restrict__ off,
        const int* __restrict__ srcs, float4* __restrict__ agg,
        const float* __restrict__ xb,
        const float* __restrict__ Wc, const float* __restrict__ bc,
        const float* __restrict__ WR, const float* __restrict__ bR,
        const float* __restrict__ Wt, const float* __restrict__ bt,
        const float* __restrict__ pos_in,
        float* __restrict__ pos, float* __restrict__ R, float* __restrict__ tv,
        int n, int nAggBlocks, int first) {
    int t    = threadIdx.x;
    int lane = t & 31;
    if ((int)blockIdx.x < nAggBlocks) {
        int node = blockIdx.x * 8 + (t >> 5);
        if (node >= n) return;
        aggregate_body(x, off, srcs, agg, node, lane);
    } else {
        __shared__ float sWp[13 * D];
        load_proj_weights(sWp, Wc, WR, Wt, t, 256);
        __syncthreads();
        int node = (blockIdx.x - nAggBlocks) * 8 + (t >> 5);
        if (node >= n) return;
        node_update_body(xb, sWp, bc, bR, bt, pos_in, pos, R, tv, node, lane, first);
    }
}

// ---------------- single-phase 3xTF32 GEMM ----------------
#define SAR 132
#define SWR 136
#define GEMM_SMEM_FLOATS (128 * SAR + 128 * SWR)

__device__ __forceinline__ void split_tf32(float a, unsigned& hi, unsigned& lo) {
    asm("cvt.rna.tf32.f32 %0, %1;" : "=r"(hi) : "f"(a));
    float r = a - __uint_as_float(hi);
    asm("cvt.rna.tf32.f32 %0, %1;" : "=r"(lo) : "f"(r));
}

__device__ __forceinline__ void mma_tf32(float* c, const unsigned* a, const unsigned* b) {
    asm volatile(
        "mma.sync.aligned.m16n8k8.row.col.f32.tf32.tf32.f32 "
        "{%0,%1,%2,%3},{%4,%5,%6,%7},{%8,%9},{%0,%1,%2,%3};"
        : "+f"(c[0]), "+f"(c[1]), "+f"(c[2]), "+f"(c[3])
        : "r"(a[0]), "r"(a[1]), "r"(a[2]), "r"(a[3]), "r"(b[0]), "r"(b[1]));
}

__global__ __launch_bounds__(512) void gemm_tc(
        const float* __restrict__ A, const float* __restrict__ W,
        const float* __restrict__ bias, const int* __restrict__ off,
        float* __restrict__ out, int n) {
    extern __shared__ float sm[];
    float* sA = sm;
    float* sW = sm + 128 * SAR;

    int t    = threadIdx.x;
    int warp = t >> 5;
    int lane = t & 31;
    int gid  = lane >> 2;
    int tg   = lane & 3;
    int wm   = warp & 3;
    int wn   = warp >> 2;
    int row0 = blockIdx.x * 128;
    int m0   = wm * 32;
    int n0   = wn * 32;

#pragma unroll
    for (int q = 0; q < 8; q++) {
        int fid = t + q * 512;
        int r   = fid >> 5;
        int kc  = (fid & 31) * 4;
        float4 v = make_float4(0.f, 0.f, 0.f, 0.f);
        if (row0 + r < n) v = *(const float4*)&A[(size_t)(row0 + r) * D + kc];
        *(float4*)&sA[r * SAR + kc] = v;
    }
#pragma unroll
    for (int q = 0; q < 8; q++) {
        int fid = t + q * 512;
        int k   = fid >> 5;
        int nc  = (fid & 31) * 4;
        *(float4*)&sW[k * SWR + nc] = *(const float4*)&W[(size_t)k * D + nc];
    }
    __syncthreads();

    float c[2][4][4];
#pragma unroll
    for (int mi = 0; mi < 2; mi++)
#pragma unroll
        for (int ni = 0; ni < 4; ni++)
#pragma unroll
            for (int q = 0; q < 4; q++) c[mi][ni][q] = 0.f;

#pragma unroll 4
    for (int kk = 0; kk < D; kk += 8) {
        unsigned ah[2][4], al[2][4];
#pragma unroll
        for (int mi = 0; mi < 2; mi++) {
            int r = m0 + mi * 16 + gid;
            float a0 = sA[r * SAR + kk + tg];
            float a1 = sA[(r + 8) * SAR + kk + tg];
            float a2 = sA[r * SAR + kk + tg + 4];
            float a3 = sA[(r + 8) * SAR + kk + tg + 4];
            split_tf32(a0, ah[mi][0], al[mi][0]);
            split_tf32(a1, ah[mi][1], al[mi][1]);
            split_tf32(a2, ah[mi][2], al[mi][2]);
            split_tf32(a3, ah[mi][3], al[mi][3]);
        }
        unsigned bh[4][2], bl[4][2];
#pragma unroll
        for (int ni = 0; ni < 4; ni++) {
            int col = n0 + ni * 8 + gid;
            float b0 = sW[(kk + tg) * SWR + col];
            float b1 = sW[(kk + tg + 4) * SWR + col];
            split_tf32(b0, bh[ni][0], bl[ni][0]);
            split_tf32(b1, bh[ni][1], bl[ni][1]);
        }
#pragma unroll
        for (int mi = 0; mi < 2; mi++)
#pragma unroll
            for (int ni = 0; ni < 4; ni++) {
                mma_tf32(c[mi][ni], ah[mi], bh[ni]);
                mma_tf32(c[mi][ni], al[mi], bh[ni]);
                mma_tf32(c[mi][ni], ah[mi], bl[ni]);
            }
    }

#pragma unroll
    for (int mi = 0; mi < 2; mi++) {
        int r0 = row0 + m0 + mi * 16 + gid;
        int r1 = r0 + 8;
        float f0 = 1.f, f1 = 1.f;
        if (off) {
            if (r0 < n) f0 = (float)(__ldg(&off[r0 + 1]) - __ldg(&off[r0]));
            if (r1 < n) f1 = (float)(__ldg(&off[r1 + 1]) - __ldg(&off[r1]));
        }
#pragma unroll
        for (int ni = 0; ni < 4; ni++) {
            int col = n0 + ni * 8 + tg * 2;
            float b0 = bias[col], b1 = bias[col + 1];
            if (r0 < n) {
                float2 o = make_float2(c[mi][ni][0] + f0 * b0, c[mi][ni][1] + f0 * b1);
                *(float2*)&out[(size_t)r0 * D + col] = o;
            }
            if (r1 < n) {
                float2 o = make_float2(c[mi][ni][2] + f1 * b0, c[mi][ni][3] + f1 * b1);
                *(float2*)&out[(size_t)r1 * D + col] = o;
            }
        }
    }
}

// ---------------- launch ----------------
extern "C" void kernel_launch(void* const* d_in, const int* in_sizes, int n_in,
                              void* d_out, int out_size) {
    const float* x   = (const float*)d_in[0];
    const float* pos = (const float*)d_in[1];
    const int*   ei  = (const int*)d_in[2];
    const float* Wl  = (const float*)d_in[3];
    const float* bl  = (const float*)d_in[4];
    const float* Wc  = (const float*)d_in[5];
    const float* bc  = (const float*)d_in[6];
    const float* WR  = (const float*)d_in[7];
    const float* bR  = (const float*)d_in[8];
    const float* Wt  = (const float*)d_in[9];
    const float* bt  = (const float*)d_in[10];
    const float* Wf  = (const float*)d_in[11];
    const float* bf  = (const float*)d_in[12];

    int n = in_sizes[0] / D;
    int E = in_sizes[2] / 2;
    const int* src = ei;
    const int* dst = ei + E;

    float* zout = (float*)d_out;
    float* pout = zout + (size_t)n * D;
    float* Rout = pout + (size_t)n * 3;
    float* tout = Rout + (size_t)n * 9;

    float *agg, *xb;
    int *cnt, *off, *srcs, *bsum;
    cudaGetSymbolAddress((void**)&agg,  g_agg);
    cudaGetSymbolAddress((void**)&xb,   g_xb);
    cudaGetSymbolAddress((void**)&cnt,  g_cnt);
    cudaGetSymbolAddress((void**)&off,  g_off);
    cudaGetSymbolAddress((void**)&srcs, g_srcs);
    cudaGetSymbolAddress((void**)&bsum, g_bsum);

    int gemm_smem = GEMM_SMEM_FLOATS * 4;
    cudaFuncSetAttribute(gemm_tc, cudaFuncAttributeMaxDynamicSharedMemorySize, gemm_smem);

    int nb = (n + SCAN_BS - 1) / SCAN_BS;   // scan blocks (<=1024 assumed; n=50k -> 196)

    // ---- CSR build ----
    // invariant: cnt[] is all-zero on entry (zero-init first call; restored below each call)
    hist_kernel<<<(E + 255) / 256, 256>>>(dst, cnt, E);
    scan1_kernel<<<nb, SCAN_BS>>>(cnt, off, bsum, n);
    scan2_kernel<<<1, 1024>>>(bsum, nb);
    scan3_kernel<<<nb, SCAN_BS>>>(cnt, off, bsum, n, E);   // also resets cnt -> cursor
    fill_kernel<<<(E + 255) / 256, 256>>>(src, dst, off, cnt, srcs, E);
    reset_cnt_kernel<<<nb, SCAN_BS>>>(cnt, n);             // restore zero-invariant

    int gblocks = (n + 127) / 128;
    int ablocks = (n + 7) / 8;
    int ublocks = (n + 7) / 8;

    // layer 0
    aggregate_kernel<<<ablocks, 256>>>((const float4*)x, off, srcs, (float4*)agg, n);
    gemm_tc<<<gblocks, 512, gemm_smem>>>(agg, Wl, bl, off, xb, n);

    // layers 1..L-1: [aggregate(l) || node_update(l-1)], then gemm(l)
    for (int l = 1; l < NLAYERS; l++) {
        int pl = l - 1;
        agg_update_kernel<<<ablocks + ublocks, 256>>>(
            (const float4*)xb, off, srcs, (float4*)agg, xb,
            Wc + (size_t)pl * D,      bc + pl,
            WR + (size_t)pl * D * 9,  bR + (size_t)pl * 9,
            Wt + (size_t)pl * D * 3,  bt + (size_t)pl * 3,
            pos, pout, Rout, tout, n, ablocks, pl == 0 ? 1 : 0);
        gemm_tc<<<gblocks, 512, gemm_smem>>>(agg, Wl + (size_t)l * D * D, bl + (size_t)l * D,
                                             off, xb, n);
    }

    // final: node_update(last layer), then fc GEMM
    {
        int pl = NLAYERS - 1;
        node_update_kernel<<<ublocks, 256>>>(xb,
            Wc + (size_t)pl * D,      bc + pl,
            WR + (size_t)pl * D * 9,  bR + (size_t)pl * 9,
            Wt + (size_t)pl * D * 3,  bt + (size_t)pl * 3,
            pout, Rout, tout, n);
    }
    gemm_tc<<<gblocks, 512, gemm_smem>>>(xb, Wf, bf, nullptr, zout, n);
}

// round 15
// speedup vs baseline: 1.2812x; 1.2812x over previous
#include <cuda_runtime.h>
#include <cstdint>

#define D        128
#define CD       3
#define NLAYERS  3
#define MAXN     65536
#define MAXE     1048576

// ---------------- scratch ----------------
__device__ float g_agg [(size_t)MAXN * D];
__device__ float g_xb  [(size_t)MAXN * D];
__device__ int   g_cnt [MAXN];
__device__ int   g_off [MAXN + 1];
__device__ int   g_srcs[MAXE];

// ---------------- CSR build ----------------
__global__ void hist_kernel(const int* __restrict__ dst, int* __restrict__ cnt, int E) {
    int i = blockIdx.x * blockDim.x + threadIdx.x;
    if (i < E) atomicAdd(&cnt[dst[i]], 1);
}

__global__ __launch_bounds__(1024) void scan_kernel(int* __restrict__ cnt, int* __restrict__ off,
                                                    int n, int E) {
    __shared__ int ssum[1024];
    int t = threadIdx.x;
    int C = (n + 1023) / 1024;
    int lo = t * C, hi = min(lo + C, n);
    int s = 0;
    for (int i = lo; i < hi; i++) s += cnt[i];
    ssum[t] = s;
    __syncthreads();
    for (int d = 1; d < 1024; d <<= 1) {
        int v = (t >= d) ? ssum[t - d] : 0;
        __syncthreads();
        ssum[t] += v;
        __syncthreads();
    }
    int base = ssum[t] - s;
    for (int i = lo; i < hi; i++) {
        int c = cnt[i];
        off[i] = base;
        cnt[i] = 0;
        base += c;
    }
    if (t == 1023) off[n] = E;
}

__global__ void fill_kernel(const int* __restrict__ src, const int* __restrict__ dst,
                            const int* __restrict__ off, int* __restrict__ cur,
                            int* __restrict__ srcs, int E) {
    int e = blockIdx.x * blockDim.x + threadIdx.x;
    if (e >= E) return;
    int d = dst[e];
    int p = atomicAdd(&cur[d], 1);
    srcs[off[d] + p] = src[e];
}

// ---------------- 3x3 Householder QR (LAPACK dlarfg convention) ----------------
__device__ __forceinline__ void qr3(const float A0[9], float Q[9]) {
    float a[9];
#pragma unroll
    for (int i = 0; i < 9; i++) a[i] = A0[i];

    float tau1 = 0.f, v1 = 0.f, v2 = 0.f;
    {
        float c0 = a[0], c1 = a[3], c2 = a[6];
        float xn2 = c1 * c1 + c2 * c2;
        if (xn2 > 0.f) {
            float nrm  = sqrtf(c0 * c0 + xn2);
            float beta = -copysignf(nrm, c0);
            tau1 = (beta - c0) / beta;
            float inv = 1.f / (c0 - beta);
            v1 = c1 * inv;
            v2 = c2 * inv;
#pragma unroll
            for (int c = 1; c < 3; c++) {
                float w = a[c] + v1 * a[3 + c] + v2 * a[6 + c];
                w *= tau1;
                a[c]     -= w;
                a[3 + c] -= w * v1;
                a[6 + c] -= w * v2;
            }
        }
    }
    float tau2 = 0.f, u2 = 0.f;
    {
        float alpha = a[4], x2 = a[7];
        if (x2 != 0.f) {
            float nrm  = sqrtf(alpha * alpha + x2 * x2);
            float beta = -copysignf(nrm, alpha);
            tau2 = (beta - alpha) / beta;
            u2   = x2 / (alpha - beta);
        }
    }
    float h11 = 1.f - tau2;
    float h12 = -tau2 * u2;
    float h22 = 1.f - tau2 * u2 * u2;
#pragma unroll
    for (int j = 0; j < 3; j++) {
        float h0 = (j == 0) ? 1.f : 0.f;
        float h1 = (j == 0) ? 0.f : ((j == 1) ? h11 : h12);
        float h2 = (j == 0) ? 0.f : ((j == 1) ? h12 : h22);
        float w  = tau1 * (h0 + v1 * h1 + v2 * h2);
        Q[0 * 3 + j] = h0 - w;
        Q[1 * 3 + j] = h1 - v1 * w;
        Q[2 * 3 + j] = h2 - v2 * w;
    }
}

// ---------------- node update device body (warp-per-node) ----------------
__device__ __forceinline__ void node_update_body(
        const float* __restrict__ out, const float* sWp,
        const float* __restrict__ bc, const float* __restrict__ bR,
        const float* __restrict__ bt, const float* __restrict__ pos_in,
        float* __restrict__ pos, float* __restrict__ R, float* __restrict__ tv,
        int node, int lane, int first) {
    float4 xv = *(const float4*)&out[(size_t)node * D + lane * 4];
    float p[13];
#pragma unroll
    for (int j = 0; j < 13; j++) {
        float4 w = ((const float4*)&sWp[j * D])[lane];
        float s = xv.x * w.x + xv.y * w.y + xv.z * w.z + xv.w * w.w;
        s += __shfl_xor_sync(0xFFFFFFFF, s, 16);
        s += __shfl_xor_sync(0xFFFFFFFF, s, 8);
        s += __shfl_xor_sync(0xFFFFFFFF, s, 4);
        s += __shfl_xor_sync(0xFFFFFFFF, s, 2);
        s += __shfl_xor_sync(0xFFFFFFFF, s, 1);
        p[j] = s;
    }
    if (lane == 0) {
        float c = p[0] + bc[0];
        if (first) {
            pos[node * 3 + 0] = pos_in[node * 3 + 0] + c;
            pos[node * 3 + 1] = pos_in[node * 3 + 1] + c;
            pos[node * 3 + 2] = pos_in[node * 3 + 2] + c;
            tv[node * 3 + 0] = p[10] + bt[0];
            tv[node * 3 + 1] = p[11] + bt[1];
            tv[node * 3 + 2] = p[12] + bt[2];
        } else {
            pos[node * 3 + 0] += c;
            pos[node * 3 + 1] += c;
            pos[node * 3 + 2] += c;
            tv[node * 3 + 0] += p[10] + bt[0];
            tv[node * 3 + 1] += p[11] + bt[1];
            tv[node * 3 + 2] += p[12] + bt[2];
        }
        float Aq[9], Q[9];
#pragma unroll
        for (int i = 0; i < 9; i++) Aq[i] = p[1 + i] + bR[i];
        qr3(Aq, Q);
        if (first) {
#pragma unroll
            for (int i = 0; i < 9; i++) R[(size_t)node * 9 + i] = Q[i];
        } else {
            float Ro[9];
#pragma unroll
            for (int i = 0; i < 9; i++) Ro[i] = R[(size_t)node * 9 + i];
            float Rn[9];
#pragma unroll
            for (int i = 0; i < 3; i++)
#pragma unroll
                for (int j = 0; j < 3; j++)
                    Rn[i * 3 + j] = Q[i * 3 + 0] * Ro[0 * 3 + j]
                                  + Q[i * 3 + 1] * Ro[1 * 3 + j]
                                  + Q[i * 3 + 2] * Ro[2 * 3 + j];
#pragma unroll
            for (int i = 0; i < 9; i++) R[(size_t)node * 9 + i] = Rn[i];
        }
    }
}

__device__ __forceinline__ void load_proj_weights(
        float* sWp, const float* __restrict__ Wc, const float* __restrict__ WR,
        const float* __restrict__ Wt, int t, int nthreads) {
    for (int i = t; i < 13 * D; i += nthreads) {
        int j = i >> 7, k = i & 127;
        float v;
        if (j == 0)      v = Wc[k];
        else if (j < 10) v = WR[k * 9 + (j - 1)];
        else             v = Wt[k * 3 + (j - 10)];
        sWp[j * D + k] = v;
    }
}

// ---------------- aggregate device body (warp-per-node) ----------------
__device__ __forceinline__ void aggregate_body(
        const float4* __restrict__ x, const int* __restrict__ off,
        const int* __restrict__ srcs, float4* __restrict__ agg, int node, int lane) {
    int j0 = __ldg(&off[node]);
    int j1 = __ldg(&off[node + 1]);
    float4 acc = make_float4(0.f, 0.f, 0.f, 0.f);
    int j = j0;
    for (; j + 4 <= j1; j += 4) {
        int s0 = __ldg(&srcs[j + 0]);
        int s1 = __ldg(&srcs[j + 1]);
        int s2 = __ldg(&srcs[j + 2]);
        int s3 = __ldg(&srcs[j + 3]);
        float4 v0 = __ldg(&x[(size_t)s0 * 32 + lane]);
        float4 v1 = __ldg(&x[(size_t)s1 * 32 + lane]);
        float4 v2 = __ldg(&x[(size_t)s2 * 32 + lane]);
        float4 v3 = __ldg(&x[(size_t)s3 * 32 + lane]);
        acc.x += v0.x + v1.x + v2.x + v3.x;
        acc.y += v0.y + v1.y + v2.y + v3.y;
        acc.z += v0.z + v1.z + v2.z + v3.z;
        acc.w += v0.w + v1.w + v2.w + v3.w;
    }
    for (; j < j1; j++) {
        int s = __ldg(&srcs[j]);
        float4 v = __ldg(&x[(size_t)s * 32 + lane]);
        acc.x += v.x; acc.y += v.y; acc.z += v.z; acc.w += v.w;
    }
    agg[(size_t)node * 32 + lane] = acc;
}

// ---------------- plain aggregate ----------------
__global__ __launch_bounds__(256) void aggregate_kernel(
        const float4* __restrict__ x, const int* __restrict__ off,
        const int* __restrict__ srcs, float4* __restrict__ agg, int n) {
    int node = blockIdx.x * 8 + (threadIdx.x >> 5);
    if (node >= n) return;
    aggregate_body(x, off, srcs, agg, node, threadIdx.x & 31);
}

// ---------------- standalone node_update ----------------
__global__ __launch_bounds__(256) void node_update_kernel(
        const float* __restrict__ out,
        const float* __restrict__ Wc, const float* __restrict__ bc,
        const float* __restrict__ WR, const float* __restrict__ bR,
        const float* __restrict__ Wt, const float* __restrict__ bt,
        float* __restrict__ pos, float* __restrict__ R, float* __restrict__ tv, int n) {
    __shared__ float sWp[13 * D];
    int t = threadIdx.x;
    load_proj_weights(sWp, Wc, WR, Wt, t, 256);
    __syncthreads();
    int node = blockIdx.x * 8 + (t >> 5);
    if (node >= n) return;
    node_update_body(out, sWp, bc, bR, bt, nullptr, pos, R, tv, node, t & 31, 0);
}

// ---------------- fat kernel: aggregate(l+1) || node_update(l) ----------------
__global__ __launch_bounds__(256) void agg_update_kernel(
        const float4* __restrict__ x, const int* __restrict__ off,
        const int* __restrict__ srcs, float4* __restrict__ agg,
        const float* __restrict__ xb,
        const float* __restrict__ Wc, const float* __restrict__ bc,
        const float* __restrict__ WR, const float* __restrict__ bR,
        const float* __restrict__ Wt, const float* __restrict__ bt,
        const float* __restrict__ pos_in,
        float* __restrict__ pos, float* __restrict__ R, float* __restrict__ tv,
        int n, int nAggBlocks, int first) {
    int t    = threadIdx.x;
    int lane = t & 31;
    if ((int)blockIdx.x < nAggBlocks) {
        int node = blockIdx.x * 8 + (t >> 5);
        if (node >= n) return;
        aggregate_body(x, off, srcs, agg, node, lane);
    } else {
        __shared__ float sWp[13 * D];
        load_proj_weights(sWp, Wc, WR, Wt, t, 256);
        __syncthreads();
        int node = (blockIdx.x - nAggBlocks) * 8 + (t >> 5);
        if (node >= n) return;
        node_update_body(xb, sWp, bc, bR, bt, pos_in, pos, R, tv, node, lane, first);
    }
}

// ---------------- single-phase 3xTF32 GEMM ----------------
#define SAR 132
#define SWR 136
#define GEMM_SMEM_FLOATS (128 * SAR + 128 * SWR)

__device__ __forceinline__ void split_tf32(float a, unsigned& hi, unsigned& lo) {
    asm("cvt.rna.tf32.f32 %0, %1;" : "=r"(hi) : "f"(a));
    float r = a - __uint_as_float(hi);
    asm("cvt.rna.tf32.f32 %0, %1;" : "=r"(lo) : "f"(r));
}

__device__ __forceinline__ void mma_tf32(float* c, const unsigned* a, const unsigned* b) {
    asm volatile(
        "mma.sync.aligned.m16n8k8.row.col.f32.tf32.tf32.f32 "
        "{%0,%1,%2,%3},{%4,%5,%6,%7},{%8,%9},{%0,%1,%2,%3};"
        : "+f"(c[0]), "+f"(c[1]), "+f"(c[2]), "+f"(c[3])
        : "r"(a[0]), "r"(a[1]), "r"(a[2]), "r"(a[3]), "r"(b[0]), "r"(b[1]));
}

__global__ __launch_bounds__(512) void gemm_tc(
        const float* __restrict__ A, const float* __restrict__ W,
        const float* __restrict__ bias, const int* __restrict__ off,
        float* __restrict__ out, int n) {
    extern __shared__ float sm[];
    float* sA = sm;
    float* sW = sm + 128 * SAR;

    int t    = threadIdx.x;
    int warp = t >> 5;
    int lane = t & 31;
    int gid  = lane >> 2;
    int tg   = lane & 3;
    int wm   = warp & 3;
    int wn   = warp >> 2;
    int row0 = blockIdx.x * 128;
    int m0   = wm * 32;
    int n0   = wn * 32;

#pragma unroll
    for (int q = 0; q < 8; q++) {
        int fid = t + q * 512;
        int r   = fid >> 5;
        int kc  = (fid & 31) * 4;
        float4 v = make_float4(0.f, 0.f, 0.f, 0.f);
        if (row0 + r < n) v = *(const float4*)&A[(size_t)(row0 + r) * D + kc];
        *(float4*)&sA[r * SAR + kc] = v;
    }
#pragma unroll
    for (int q = 0; q < 8; q++) {
        int fid = t + q * 512;
        int k   = fid >> 5;
        int nc  = (fid & 31) * 4;
        *(float4*)&sW[k * SWR + nc] = *(const float4*)&W[(size_t)k * D + nc];
    }
    __syncthreads();

    float c[2][4][4];
#pragma unroll
    for (int mi = 0; mi < 2; mi++)
#pragma unroll
        for (int ni = 0; ni < 4; ni++)
#pragma unroll
            for (int q = 0; q < 4; q++) c[mi][ni][q] = 0.f;

#pragma unroll 4
    for (int kk = 0; kk < D; kk += 8) {
        unsigned ah[2][4], al[2][4];
#pragma unroll
        for (int mi = 0; mi < 2; mi++) {
            int r = m0 + mi * 16 + gid;
            float a0 = sA[r * SAR + kk + tg];
            float a1 = sA[(r + 8) * SAR + kk + tg];
            float a2 = sA[r * SAR + kk + tg + 4];
            float a3 = sA[(r + 8) * SAR + kk + tg + 4];
            split_tf32(a0, ah[mi][0], al[mi][0]);
            split_tf32(a1, ah[mi][1], al[mi][1]);
            split_tf32(a2, ah[mi][2], al[mi][2]);
            split_tf32(a3, ah[mi][3], al[mi][3]);
        }
        unsigned bh[4][2], bl[4][2];
#pragma unroll
        for (int ni = 0; ni < 4; ni++) {
            int col = n0 + ni * 8 + gid;
            float b0 = sW[(kk + tg) * SWR + col];
            float b1 = sW[(kk + tg + 4) * SWR + col];
            split_tf32(b0, bh[ni][0], bl[ni][0]);
            split_tf32(b1, bh[ni][1], bl[ni][1]);
        }
#pragma unroll
        for (int mi = 0; mi < 2; mi++)
#pragma unroll
            for (int ni = 0; ni < 4; ni++) {
                mma_tf32(c[mi][ni], ah[mi], bh[ni]);
                mma_tf32(c[mi][ni], al[mi], bh[ni]);
                mma_tf32(c[mi][ni], ah[mi], bl[ni]);
            }
    }

#pragma unroll
    for (int mi = 0; mi < 2; mi++) {
        int r0 = row0 + m0 + mi * 16 + gid;
        int r1 = r0 + 8;
        float f0 = 1.f, f1 = 1.f;
        if (off) {
            if (r0 < n) f0 = (float)(__ldg(&off[r0 + 1]) - __ldg(&off[r0]));
            if (r1 < n) f1 = (float)(__ldg(&off[r1 + 1]) - __ldg(&off[r1]));
        }
#pragma unroll
        for (int ni = 0; ni < 4; ni++) {
            int col = n0 + ni * 8 + tg * 2;
            float b0 = bias[col], b1 = bias[col + 1];
            if (r0 < n) {
                float2 o = make_float2(c[mi][ni][0] + f0 * b0, c[mi][ni][1] + f0 * b1);
                *(float2*)&out[(size_t)r0 * D + col] = o;
            }
            if (r1 < n) {
                float2 o = make_float2(c[mi][ni][2] + f1 * b0, c[mi][ni][3] + f1 * b1);
                *(float2*)&out[(size_t)r1 * D + col] = o;
            }
        }
    }
}

// ---------------- launch ----------------
extern "C" void kernel_launch(void* const* d_in, const int* in_sizes, int n_in,
                              void* d_out, int out_size) {
    const float* x   = (const float*)d_in[0];
    const float* pos = (const float*)d_in[1];
    const int*   ei  = (const int*)d_in[2];
    const float* Wl  = (const float*)d_in[3];
    const float* bl  = (const float*)d_in[4];
    const float* Wc  = (const float*)d_in[5];
    const float* bc  = (const float*)d_in[6];
    const float* WR  = (const float*)d_in[7];
    const float* bR  = (const float*)d_in[8];
    const float* Wt  = (const float*)d_in[9];
    const float* bt  = (const float*)d_in[10];
    const float* Wf  = (const float*)d_in[11];
    const float* bf  = (const float*)d_in[12];

    int n = in_sizes[0] / D;
    int E = in_sizes[2] / 2;
    const int* src = ei;
    const int* dst = ei + E;

    float* zout = (float*)d_out;
    float* pout = zout + (size_t)n * D;
    float* Rout = pout + (size_t)n * 3;
    float* tout = Rout + (size_t)n * 9;

    float *agg, *xb;
    int *cnt, *off, *srcs;
    cudaGetSymbolAddress((void**)&agg,  g_agg);
    cudaGetSymbolAddress((void**)&xb,   g_xb);
    cudaGetSymbolAddress((void**)&cnt,  g_cnt);
    cudaGetSymbolAddress((void**)&off,  g_off);
    cudaGetSymbolAddress((void**)&srcs, g_srcs);

    int gemm_smem = GEMM_SMEM_FLOATS * 4;
    cudaFuncSetAttribute(gemm_tc, cudaFuncAttributeMaxDynamicSharedMemorySize, gemm_smem);

    // ---- CSR build ----
    cudaMemsetAsync(cnt, 0, (size_t)n * sizeof(int), 0);
    hist_kernel<<<(E + 255) / 256, 256>>>(dst, cnt, E);
    scan_kernel<<<1, 1024>>>(cnt, off, n, E);
    fill_kernel<<<(E + 255) / 256, 256>>>(src, dst, off, cnt, srcs, E);

    int gblocks = (n + 127) / 128;
    int ablocks = (n + 7) / 8;
    int ublocks = (n + 7) / 8;

    // layer 0
    aggregate_kernel<<<ablocks, 256>>>((const float4*)x, off, srcs, (float4*)agg, n);
    gemm_tc<<<gblocks, 512, gemm_smem>>>(agg, Wl, bl, off, xb, n);

    // layers 1..L-1: [aggregate(l) || node_update(l-1)], then gemm(l)
    for (int l = 1; l < NLAYERS; l++) {
        int pl = l - 1;
        agg_update_kernel<<<ablocks + ublocks, 256>>>(
            (const float4*)xb, off, srcs, (float4*)agg, xb,
            Wc + (size_t)pl * D,      bc + pl,
            WR + (size_t)pl * D * 9,  bR + (size_t)pl * 9,
            Wt + (size_t)pl * D * 3,  bt + (size_t)pl * 3,
            pos, pout, Rout, tout, n, ablocks, pl == 0 ? 1 : 0);
        gemm_tc<<<gblocks, 512, gemm_smem>>>(agg, Wl + (size_t)l * D * D, bl + (size_t)l * D,
                                             off, xb, n);
    }

    // final: node_update(last layer), then fc GEMM
    {
        int pl = NLAYERS - 1;
        node_update_kernel<<<ublocks, 256>>>(xb,
            Wc + (size_t)pl * D,      bc + pl,
            WR + (size_t)pl * D * 9,  bR + (size_t)pl * 9,
            Wt + (size_t)pl * D * 3,  bt + (size_t)pl * 3,
            pout, Rout, tout, n);
    }
    gemm_tc<<<gblocks, 512, gemm_smem>>>(xb, Wf, bf, nullptr, zout, n);
}